// round 1
// baseline (speedup 1.0000x reference)
#include <cuda_runtime.h>
#include <cuda_bf16.h>
#include <cstdint>

// Problem: out = P5(x) / Q4(x), elementwise over x[B=4, L=4096, D=2048].
//   P5 coeffs a[0..5]   : shared across all groups (weight_numerator, 6 floats)
//   Q4 coeffs           : [1, |b1|, |b2|, |b3|, |b4|] per group g (8 groups, 4 floats each)
//   group g = (flat_idx % 2048) / 256  -> on the float4 index: (v4 >> 6) & 7
//
// Pure streaming kernel: 16B load + 16B store per thread, coefficients L1-cached.

#define THREADS 256

__global__ __launch_bounds__(THREADS, 8)
void kat_rational_kernel(const float4* __restrict__ x4,
                         const float*  __restrict__ wnum,   // 6 floats
                         const float*  __restrict__ wden,   // 8*4 floats (g-major)
                         float4* __restrict__ out4,
                         int n4)                            // number of float4s
{
    int idx = blockIdx.x * THREADS + threadIdx.x;
    if (idx >= n4) return;

    // D = 2048 floats = 512 float4s per row; group chunk = 256 floats = 64 float4s.
    // g = (idx mod 512) / 64 = (idx >> 6) & 7
    int g = (idx >> 6) & 7;

    // Numerator coefficients (shared) — uniform across warp, L1/const-cached.
    float a0 = __ldg(wnum + 0);
    float a1 = __ldg(wnum + 1);
    float a2 = __ldg(wnum + 2);
    float a3 = __ldg(wnum + 3);
    float a4 = __ldg(wnum + 4);
    float a5 = __ldg(wnum + 5);

    // Denominator coefficients |b1..b4| for this group; c0 = |1| = 1.
    const float* bg = wden + g * 4;
    float c1 = fabsf(__ldg(bg + 0));
    float c2 = fabsf(__ldg(bg + 1));
    float c3 = fabsf(__ldg(bg + 2));
    float c4 = fabsf(__ldg(bg + 3));

    float4 v = x4[idx];
    float4 r;

    {
        float z = v.x;
        float num = fmaf(fmaf(fmaf(fmaf(fmaf(a5, z, a4), z, a3), z, a2), z, a1), z, a0);
        float den = fmaf(fmaf(fmaf(fmaf(c4, z, c3), z, c2), z, c1), z, 1.0f);
        r.x = __fdividef(num, den);
    }
    {
        float z = v.y;
        float num = fmaf(fmaf(fmaf(fmaf(fmaf(a5, z, a4), z, a3), z, a2), z, a1), z, a0);
        float den = fmaf(fmaf(fmaf(fmaf(c4, z, c3), z, c2), z, c1), z, 1.0f);
        r.y = __fdividef(num, den);
    }
    {
        float z = v.z;
        float num = fmaf(fmaf(fmaf(fmaf(fmaf(a5, z, a4), z, a3), z, a2), z, a1), z, a0);
        float den = fmaf(fmaf(fmaf(fmaf(c4, z, c3), z, c2), z, c1), z, 1.0f);
        r.z = __fdividef(num, den);
    }
    {
        float z = v.w;
        float num = fmaf(fmaf(fmaf(fmaf(fmaf(a5, z, a4), z, a3), z, a2), z, a1), z, a0);
        float den = fmaf(fmaf(fmaf(fmaf(c4, z, c3), z, c2), z, c1), z, 1.0f);
        r.w = __fdividef(num, den);
    }

    out4[idx] = r;
}

extern "C" void kernel_launch(void* const* d_in, const int* in_sizes, int n_in,
                              void* d_out, int out_size)
{
    // metadata order: x (float32, B*L*D), weight_numerator (float32, 6),
    //                 weight_denominator (float32, 32), num_groups (int, scalar)
    const float* x    = (const float*)d_in[0];
    const float* wnum = (const float*)d_in[1];
    const float* wden = (const float*)d_in[2];
    float* out        = (float*)d_out;

    int n  = in_sizes[0];     // 33,554,432
    int n4 = n >> 2;          // exactly divisible (D=2048)

    int blocks = (n4 + THREADS - 1) / THREADS;
    kat_rational_kernel<<<blocks, THREADS>>>((const float4*)x, wnum, wden,
                                             (float4*)out, n4);
}

// round 2
// speedup vs baseline: 1.0476x; 1.0476x over previous
#include <cuda_runtime.h>
#include <cuda_bf16.h>
#include <cstdint>

// out = P5(x) / Q4(x) elementwise over x[4, 4096, 2048], 8 groups of 256 along D.
//   numerator a[0..5] shared; denominator [1, |b1|..|b4|] per group.
// Streaming kernel, ITEMS=4 float4 per thread (64B in / 64B out), MLP=4.

#define THREADS 256
#define ITEMS   4   // float4s per thread, strided by THREADS

__device__ __forceinline__ float rational(float z,
    float a0, float a1, float a2, float a3, float a4, float a5,
    float c1, float c2, float c3, float c4)
{
    float num = fmaf(fmaf(fmaf(fmaf(fmaf(a5, z, a4), z, a3), z, a2), z, a1), z, a0);
    float den = fmaf(fmaf(fmaf(fmaf(c4, z, c3), z, c2), z, c1), z, 1.0f);
    return __fdividef(num, den);
}

__global__ __launch_bounds__(THREADS, 6)
void kat_rational_kernel(const float4* __restrict__ x4,
                         const float*  __restrict__ wnum,   // 6 floats
                         const float*  __restrict__ wden,   // 8*4 floats
                         float4* __restrict__ out4,
                         int n4)
{
    int base = blockIdx.x * (THREADS * ITEMS) + threadIdx.x;

    // ---- Batch all stream loads first (MLP = ITEMS) ----
    float4 v[ITEMS];
    bool ok[ITEMS];
    #pragma unroll
    for (int j = 0; j < ITEMS; ++j) {
        int idx = base + j * THREADS;
        ok[j] = (idx < n4);
        if (ok[j]) v[j] = __ldcs(&x4[idx]);
    }

    // ---- Coefficients (warp-uniform broadcasts) ----
    float a0 = __ldg(wnum + 0), a1 = __ldg(wnum + 1), a2 = __ldg(wnum + 2);
    float a3 = __ldg(wnum + 3), a4 = __ldg(wnum + 4), a5 = __ldg(wnum + 5);

    // group of float4 idx: g = (idx >> 6) & 7 (64 float4 per group chunk).
    // item stride THREADS=256 float4 = 4 chunks -> g_j = (g0 + 4j) & 7:
    //   even j -> gA, odd j -> gB = gA ^ 4
    int gA = (base >> 6) & 7;
    int gB = gA ^ 4;

    const float* bA = wden + gA * 4;
    float cA1 = fabsf(__ldg(bA + 0)), cA2 = fabsf(__ldg(bA + 1));
    float cA3 = fabsf(__ldg(bA + 2)), cA4 = fabsf(__ldg(bA + 3));

    const float* bB = wden + gB * 4;
    float cB1 = fabsf(__ldg(bB + 0)), cB2 = fabsf(__ldg(bB + 1));
    float cB3 = fabsf(__ldg(bB + 2)), cB4 = fabsf(__ldg(bB + 3));

    // ---- Compute + store ----
    #pragma unroll
    for (int j = 0; j < ITEMS; ++j) {
        if (!ok[j]) continue;
        float c1, c2, c3, c4;
        if ((j & 1) == 0) { c1 = cA1; c2 = cA2; c3 = cA3; c4 = cA4; }
        else              { c1 = cB1; c2 = cB2; c3 = cB3; c4 = cB4; }

        float4 r;
        r.x = rational(v[j].x, a0,a1,a2,a3,a4,a5, c1,c2,c3,c4);
        r.y = rational(v[j].y, a0,a1,a2,a3,a4,a5, c1,c2,c3,c4);
        r.z = rational(v[j].z, a0,a1,a2,a3,a4,a5, c1,c2,c3,c4);
        r.w = rational(v[j].w, a0,a1,a2,a3,a4,a5, c1,c2,c3,c4);

        int idx = base + j * THREADS;
        __stcs(&out4[idx], r);
    }
}

extern "C" void kernel_launch(void* const* d_in, const int* in_sizes, int n_in,
                              void* d_out, int out_size)
{
    const float* x    = (const float*)d_in[0];
    const float* wnum = (const float*)d_in[1];
    const float* wden = (const float*)d_in[2];
    float* out        = (float*)d_out;

    int n  = in_sizes[0];     // 33,554,432
    int n4 = n >> 2;          // 8,388,608 float4s

    int per_block = THREADS * ITEMS;
    int blocks = (n4 + per_block - 1) / per_block;   // 8192
    kat_rational_kernel<<<blocks, THREADS>>>((const float4*)x, wnum, wden,
                                             (float4*)out, n4);
}